// round 13
// baseline (speedup 1.0000x reference)
#include <cuda_runtime.h>
#include <math.h>

#define BB 64
#define TT 512
#define EE 512
#define HH 512
#define G4 2048
#define KK 23
#define START_TAG 1
#define END_TAG 2
#define NEGV -10000.0f

typedef unsigned long long ull;

__device__ __forceinline__ ull pack2(float lo, float hi) {
    ull r;
    asm("mov.b64 %0, {%1, %2};" : "=l"(r) : "f"(lo), "f"(hi));
    return r;
}
__device__ __forceinline__ void unpack2(ull v, float& lo, float& hi) {
    asm("mov.b64 {%0, %1}, %2;" : "=f"(lo), "=f"(hi) : "l"(v));
}
__device__ __forceinline__ void ffma2(ull& d, ull a, ull b) {
    asm("fma.rn.f32x2 %0, %1, %2, %3;" : "=l"(d) : "l"(a), "l"(b), "l"(d));
}
__device__ __forceinline__ ull addf32x2(ull a, ull b) {
    ull r;
    asm("add.rn.f32x2 %0, %1, %2;" : "=l"(r) : "l"(a), "l"(b));
    return r;
}
__device__ __forceinline__ unsigned s2u(const void* p) {
    unsigned r;
    asm("{ .reg .u64 t; cvta.to.shared.u64 t, %1; cvt.u32.u64 %0, t; }"
        : "=r"(r) : "l"(p));
    return r;
}
__device__ __forceinline__ void st_release(unsigned* p, unsigned v) {
    asm volatile("st.release.gpu.global.u32 [%0], %1;" :: "l"(p), "r"(v) : "memory");
}
__device__ __forceinline__ unsigned ld_acquire(const unsigned* p) {
    unsigned v;
    asm volatile("ld.acquire.gpu.global.u32 %0, [%1];" : "=r"(v) : "l"(p) : "memory");
    return v;
}
#define CPASYNC16(dst, src) \
    asm volatile("cp.async.cg.shared.global [%0], [%1], 16;\n" :: "r"(dst), "l"(src))
#define CPCOMMIT() asm volatile("cp.async.commit_group;\n" ::: "memory")
#define CPWAIT(n)  asm volatile("cp.async.wait_group %0;\n" :: "n"(n) : "memory")

// ---------------- scratch ----------------
__device__ float g_xg[2][67108864];    // [dir][(b*T+t)*2048 + n]
__device__ float g_xgt[2][67108864];   // [dir][(t*2048 + n)*64 + b]
__device__ float g_hs[2][16777216];    // [dir][(t*512 + u)*64 + b]
__device__ float g_zero[HH * BB];
__device__ float g_feats[BB * TT * KK];
__device__ unsigned g_flag[128];       // per-block step flags [dir*64 + ublk]

__global__ void init_kernel() {
    int idx = blockIdx.x * blockDim.x + threadIdx.x;
    for (int i = idx; i < HH * BB; i += gridDim.x * blockDim.x) g_zero[i] = 0.0f;
    if (idx < 128) g_flag[idx] = 0u;
}

// ---------------- input GEMM (unchanged, proven) ----------------
__global__ __launch_bounds__(256, 2)
void xgemm_kernel(const float* __restrict__ A,
                  const float* __restrict__ Wf,
                  const float* __restrict__ Wb,
                  const float* __restrict__ bf,
                  const float* __restrict__ bb) {
    const int dir = blockIdx.z;
    const float* __restrict__ W = dir ? Wb : Wf;
    const float* __restrict__ bias = dir ? bb : bf;
    float* __restrict__ C = g_xg[dir];

    __shared__ __align__(16) float2 As2[8][128];
    __shared__ __align__(16) float  Bs[8][128];

    const int tid = threadIdx.x;
    const int m0 = blockIdx.y * 128;
    const int n0 = blockIdx.x * 128;
    const int lrow = tid >> 1;
    const int lkq  = (tid & 1) * 4;
    const int tx = (tid & 15) * 4;
    const int ty = (tid >> 4) * 4;

    ull acc2[8][4];
#pragma unroll
    for (int i = 0; i < 8; i++)
#pragma unroll
        for (int j = 0; j < 4; j++) acc2[i][j] = 0ull;

    for (int kt = 0; kt < EE; kt += 8) {
        float4 av = *(const float4*)(A + (size_t)(m0 + lrow) * EE + kt + lkq);
        float4 bv = *(const float4*)(W + (size_t)(n0 + lrow) * EE + kt + lkq);
        As2[lkq + 0][lrow] = make_float2(av.x, av.x);
        As2[lkq + 1][lrow] = make_float2(av.y, av.y);
        As2[lkq + 2][lrow] = make_float2(av.z, av.z);
        As2[lkq + 3][lrow] = make_float2(av.w, av.w);
        Bs[lkq + 0][lrow] = bv.x; Bs[lkq + 1][lrow] = bv.y;
        Bs[lkq + 2][lrow] = bv.z; Bs[lkq + 3][lrow] = bv.w;
        __syncthreads();
#pragma unroll
        for (int k = 0; k < 8; k++) {
            ull a[8], b[4];
            {
                ulonglong2 t0 = *(const ulonglong2*)&As2[k][ty];
                ulonglong2 t1 = *(const ulonglong2*)&As2[k][ty + 2];
                ulonglong2 t2 = *(const ulonglong2*)&As2[k][ty + 64];
                ulonglong2 t3 = *(const ulonglong2*)&As2[k][ty + 66];
                a[0] = t0.x; a[1] = t0.y; a[2] = t1.x; a[3] = t1.y;
                a[4] = t2.x; a[5] = t2.y; a[6] = t3.x; a[7] = t3.y;
                ulonglong2 u0 = *(const ulonglong2*)&Bs[k][tx];
                ulonglong2 u1 = *(const ulonglong2*)&Bs[k][tx + 64];
                b[0] = u0.x; b[1] = u0.y; b[2] = u1.x; b[3] = u1.y;
            }
#pragma unroll
            for (int i = 0; i < 8; i++)
#pragma unroll
                for (int j = 0; j < 4; j++)
                    ffma2(acc2[i][j], a[i], b[j]);
        }
        __syncthreads();
    }
    float4 bia0 = *(const float4*)(bias + n0 + tx);
    float4 bia1 = *(const float4*)(bias + n0 + tx + 64);
#pragma unroll
    for (int i = 0; i < 8; i++) {
        int m = m0 + ((i < 4) ? (ty + i) : (ty + 64 + i - 4));
        float l0, h0, l1, h1, l2, h2, l3, h3;
        unpack2(acc2[i][0], l0, h0);
        unpack2(acc2[i][1], l1, h1);
        unpack2(acc2[i][2], l2, h2);
        unpack2(acc2[i][3], l3, h3);
        float4 o0, o1;
        o0.x = l0 + bia0.x; o0.y = h0 + bia0.y;
        o0.z = l1 + bia0.z; o0.w = h1 + bia0.w;
        o1.x = l2 + bia1.x; o1.y = h2 + bia1.y;
        o1.z = l3 + bia1.z; o1.w = h3 + bia1.w;
        *(float4*)(C + (size_t)m * G4 + n0 + tx)      = o0;
        *(float4*)(C + (size_t)m * G4 + n0 + tx + 64) = o1;
    }
}

// ---------------- transpose xg: [(b*T+t)][n] -> [t][n][b] -----------------
__global__ __launch_bounds__(256, 4)
void transpose_kernel() {
    const int dir = blockIdx.z;
    const int t   = blockIdx.y;
    const int n0  = blockIdx.x * 64;
    __shared__ float s[64][65];

    const float* __restrict__ src = g_xg[dir];
    float* __restrict__ dst = g_xgt[dir];
    const int tid = threadIdx.x;

#pragma unroll
    for (int i = 0; i < 4; i++) {
        int e = i * 256 + tid;
        int b = e >> 4;
        int nf = e & 15;
        float4 v = *(const float4*)(src + ((size_t)b * TT + t) * G4 + n0 + nf * 4);
        s[b][nf * 4 + 0] = v.x; s[b][nf * 4 + 1] = v.y;
        s[b][nf * 4 + 2] = v.z; s[b][nf * 4 + 3] = v.w;
    }
    __syncthreads();
#pragma unroll
    for (int i = 0; i < 4; i++) {
        int e = i * 256 + tid;
        int nl = e >> 4;
        int bf = e & 15;
        float4 w;
        w.x = s[bf * 4 + 0][nl]; w.y = s[bf * 4 + 1][nl];
        w.z = s[bf * 4 + 2][nl]; w.w = s[bf * 4 + 3][nl];
        *(float4*)(dst + ((size_t)t * G4 + n0 + nl) * BB + bf * 4) = w;
    }
}

// ---------------- persistent bidirectional LSTM ---------------------------
// R7 core (best known): 128 blocks x 256 thr, 2-way k-split, cp.async-staged
// h chunks, smem-duplicated weights. NEW: fence-free flag barrier
// (st.release/ld.acquire, no atomics, no L1-flushing membar) + xv hoist.
__device__ __forceinline__ float sigf(float x) {
    return 1.0f / (1.0f + __expf(-x));
}
__device__ __forceinline__ float tanhfast(float x) {
    return 1.0f - 2.0f / (__expf(2.0f * x) + 1.0f);
}

#define USTR 2050
#define WB_B (8 * USTR * 8)            // 131200 bytes
#define HB_OFF WB_B                    // 2 grp x 2 buf x 8192 B = 32768... (2x16KB)
#define PART_OFF (WB_B + 65536)        // 128 x 9 ull = 9216 bytes
#define SM_TOT (PART_OFF + 9216)

__global__ __launch_bounds__(256, 1)
void lstm_persistent(const float* __restrict__ Whh_f,
                     const float* __restrict__ Whh_b) {
    const int blk  = blockIdx.x;
    const int dir  = blk >> 6;
    const int ublk = blk & 63;
    const float* __restrict__ Whh = dir ? Whh_b : Whh_f;

    extern __shared__ __align__(16) char sm[];
    float2* __restrict__ wsm = (float2*)sm;
    float*  __restrict__ hq  = (float*)(sm + HB_OFF);
    ull*    __restrict__ part = (ull*)(sm + PART_OFF);

    const int tid  = threadIdx.x;
    const int warp = tid >> 5;
    const int lane = tid & 31;
    const int kgrp = warp >> 2;            // 0 or 1 (k-half)
    const int wu2  = warp & 3;
    const int half = lane >> 4;
    const int l16  = lane & 15;
    const int gtid = tid & 127;            // id within k-group
    const int ulocal = wu2 * 2 + half;     // 0..7
    const int u = ublk * 8 + ulocal;

    // load + duplicate weights: wsm[ul*USTR + g*512 + k] = (w,w)
    for (int idx = tid; idx < 8 * 4 * HH; idx += 256) {
        int ul = idx >> 11;
        int r  = idx & 2047;
        int g  = r >> 9;
        int k  = r & 511;
        float v = Whh[(size_t)(g * HH + ublk * 8 + ul) * HH + k];
        wsm[ul * USTR + r] = make_float2(v, v);
    }
    __syncthreads();

    const float2* __restrict__ wu_ = wsm + ulocal * USTR;
    float* __restrict__ myb[2] = { hq + kgrp * 8192, hq + kgrp * 8192 + 4096 };
    const unsigned bu[2] = { s2u(myb[0]), s2u(myb[1]) };
    const float* __restrict__ xgt = g_xgt[dir];
    float* __restrict__ hsd = g_hs[dir];
    unsigned* __restrict__ flags = g_flag + dir * 64;

    float cst[4] = {0.f, 0.f, 0.f, 0.f};

    for (int s = 0; s < TT; s++) {
        const int t = dir ? (TT - 1 - s) : s;
        const float* __restrict__ hsrc = (s == 0) ? g_zero
            : (hsd + (size_t)(dir ? t + 1 : t - 1) * HH * BB);

        // group0 prefetches gate inputs BEFORE the wait (independent of h)
        float4 xv[4];
        if (kgrp == 0) {
#pragma unroll
            for (int g = 0; g < 4; g++)
                xv[g] = *(const float4*)(xgt +
                    ((size_t)t * G4 + g * HH + u) * BB + 4 * l16);
        }

        // wait: all 64 blocks of this direction have finished step s-1
        if (s > 0) {
            if (warp == 0) {
                for (;;) {
                    unsigned v0 = ld_acquire(flags + lane);
                    unsigned v1 = ld_acquire(flags + 32 + lane);
                    bool bad = (v0 < (unsigned)s) || (v1 < (unsigned)s);
                    if (!__ballot_sync(0xffffffffu, bad)) break;
                }
            }
            __syncthreads();
        }

        // stage 16KB chunk j of this k-group into buffer j&1 (group-local)
#define STAGE(j) do {                                                        \
            unsigned dstb = bu[(j) & 1];                                     \
            const float* srcb = hsrc + (kgrp * 4 + (j)) * 64 * BB;           \
            _Pragma("unroll")                                                \
            for (int i = 0; i < 8; i++) {                                    \
                int e = i * 128 + gtid;                                      \
                int kl = e >> 4, b4 = e & 15;                                \
                CPASYNC16(dstb + (kl * 64 + b4 * 4) * 4,                     \
                          srcb + kl * 64 + b4 * 4);                          \
            }                                                                \
            CPCOMMIT();                                                      \
        } while (0)
#define BARG() asm volatile("bar.sync %0, 128;" :: "r"(kgrp + 1) : "memory")

        STAGE(0);
        STAGE(1);

        ull a0[4], a1[4];
#pragma unroll
        for (int g = 0; g < 4; g++) { a0[g] = 0ull; a1[g] = 0ull; }

#pragma unroll
        for (int j = 0; j < 4; j++) {
            if (j < 3) { CPWAIT(1); } else { CPWAIT(0); }
            BARG();
            const float* __restrict__ hc = myb[j & 1];
            const int kb = (kgrp * 4 + j) * 64;
#pragma unroll 8
            for (int kk = 0; kk < 64; kk += 2) {
                const int k = kb + kk;
                ulonglong2 wi = *(const ulonglong2*)(wu_ + k);
                ulonglong2 wf = *(const ulonglong2*)(wu_ + 512 + k);
                ulonglong2 wg = *(const ulonglong2*)(wu_ + 1024 + k);
                ulonglong2 wo = *(const ulonglong2*)(wu_ + 1536 + k);
                ulonglong2 h0 = *(const ulonglong2*)&hc[kk * 64 + 4 * l16];
                ulonglong2 h1 = *(const ulonglong2*)&hc[(kk + 1) * 64 + 4 * l16];
                ffma2(a0[0], wi.x, h0.x); ffma2(a1[0], wi.x, h0.y);
                ffma2(a0[1], wf.x, h0.x); ffma2(a1[1], wf.x, h0.y);
                ffma2(a0[2], wg.x, h0.x); ffma2(a1[2], wg.x, h0.y);
                ffma2(a0[3], wo.x, h0.x); ffma2(a1[3], wo.x, h0.y);
                ffma2(a0[0], wi.y, h1.x); ffma2(a1[0], wi.y, h1.y);
                ffma2(a0[1], wf.y, h1.x); ffma2(a1[1], wf.y, h1.y);
                ffma2(a0[2], wg.y, h1.x); ffma2(a1[2], wg.y, h1.y);
                ffma2(a0[3], wo.y, h1.x); ffma2(a1[3], wo.y, h1.y);
            }
            if (j < 2) {
                BARG();          // group warps done reading buffer j&1
                STAGE(j + 2);
            }
        }
#undef STAGE

        // reduction: k-high group publishes partials, k-low finalizes
        __syncthreads();
        if (kgrp == 1) {
#pragma unroll
            for (int g = 0; g < 4; g++) {
                part[gtid * 9 + g]     = a0[g];
                part[gtid * 9 + 4 + g] = a1[g];
            }
        }
        __syncthreads();
        if (kgrp == 0) {
            float pre[4][4];
#pragma unroll
            for (int g = 0; g < 4; g++) {
                ull s0 = addf32x2(a0[g], part[gtid * 9 + g]);
                ull s1 = addf32x2(a1[g], part[gtid * 9 + 4 + g]);
                unpack2(s0, pre[g][0], pre[g][1]);
                unpack2(s1, pre[g][2], pre[g][3]);
                pre[g][0] += ((const float*)&xv[g])[0];
                pre[g][1] += ((const float*)&xv[g])[1];
                pre[g][2] += ((const float*)&xv[g])[2];
                pre[g][3] += ((const float*)&xv[g])[3];
            }
            float4 hv;
            float* hvp = (float*)&hv;
#pragma unroll
            for (int b = 0; b < 4; b++) {
                float ig = sigf(pre[0][b]);
                float fg = sigf(pre[1][b]);
                float gg = tanhfast(pre[2][b]);
                float og = sigf(pre[3][b]);
                float cn = fg * cst[b] + ig * gg;
                cst[b] = cn;
                hvp[b] = og * tanhfast(cn);
            }
            *(float4*)(hsd + ((size_t)t * HH + u) * BB + 4 * l16) = hv;
        }

        // arrive: release-store our step flag (no membar, no atomics)
        if (s != TT - 1) {
            __syncthreads();
            if (tid == 0) st_release(flags + ublk, (unsigned)(s + 1));
        }
    }
}

// ---------------- emissions: feats = [h_f, h_b] @ W_h2t^T + b_h2t ---------
__global__ __launch_bounds__(128, 2)
void feats_kernel(const float* __restrict__ Wh2t,
                  const float* __restrict__ bh2t) {
    extern __shared__ float Ws[];  // [23][1024]
    const int tid = threadIdx.x;
    for (int i = tid; i < KK * 1024; i += 128) Ws[i] = Wh2t[i];
    __syncthreads();

    const int w    = tid >> 5;
    const int lane = tid & 31;
    const int t    = blockIdx.x * 2 + (w >> 1);
    const int b    = (w & 1) * 32 + lane;

    ull acc2[KK];
#pragma unroll
    for (int k = 0; k < KK; k++) acc2[k] = 0ull;

    const float* __restrict__ hf = g_hs[0] + (size_t)t * HH * BB;
#pragma unroll 4
    for (int j = 0; j < HH; j += 2) {
        ull hp = pack2(hf[j * BB + b], hf[(j + 1) * BB + b]);
#pragma unroll
        for (int k = 0; k < KK; k++) {
            ull wp = *(const ull*)&Ws[k * 1024 + j];
            ffma2(acc2[k], wp, hp);
        }
    }
    const float* __restrict__ hbv = g_hs[1] + (size_t)t * HH * BB;
#pragma unroll 4
    for (int j = 0; j < HH; j += 2) {
        ull hp = pack2(hbv[j * BB + b], hbv[(j + 1) * BB + b]);
#pragma unroll
        for (int k = 0; k < KK; k++) {
            ull wp = *(const ull*)&Ws[k * 1024 + HH + j];
            ffma2(acc2[k], wp, hp);
        }
    }
#pragma unroll
    for (int k = 0; k < KK; k++) {
        float lo, hi;
        unpack2(acc2[k], lo, hi);
        g_feats[((size_t)b * TT + t) * KK + k] = lo + hi + __ldg(bh2t + k);
    }
}

// ---------------- Viterbi ----------------
__global__ void viterbi_kernel(const float* __restrict__ trans,
                               const int* __restrict__ seq_len,
                               float* __restrict__ out) {
    const int b    = blockIdx.x;
    const int lane = threadIdx.x;
    __shared__ unsigned char bp[TT][24];

    const int L = seq_len[b];
    const bool active = lane < KK;

    float tr[KK];
#pragma unroll
    for (int p = 0; p < KK; p++)
        tr[p] = active ? trans[lane * KK + p] : -3.0e38f;

    float fv = (lane == START_TAG) ? 0.0f : NEGV;
    const float* __restrict__ fb = g_feats + (size_t)b * TT * KK;

    for (int t = 0; t < TT; t++) {
        float ft = active ? fb[t * KK + lane] : 0.0f;
        float best = -3.4e38f;
        int arg = 0;
#pragma unroll
        for (int p = 0; p < KK; p++) {
            float v = __shfl_sync(0xffffffffu, fv, p) + tr[p];
            if (v > best) { best = v; arg = p; }
        }
        const bool m = (t < L);
        if (m) fv = best + ft;
        if (active) bp[t][lane] = m ? (unsigned char)arg : (unsigned char)lane;
    }

    float term = active ? (fv + trans[END_TAG * KK + lane]) : -3.4e38f;
    float bestv = -3.4e38f;
    int btag = 0;
#pragma unroll
    for (int p = 0; p < KK; p++) {
        float v = __shfl_sync(0xffffffffu, term, p);
        if (v > bestv) { bestv = v; btag = p; }
    }

    if (lane == 0) {
        out[b] = bestv;
        int tag = btag;
        out[BB + (size_t)b * TT + (TT - 1)] = (float)tag;
        for (int t = TT - 1; t >= 1; t--) {
            tag = bp[t][tag];
            out[BB + (size_t)b * TT + (t - 1)] = (float)tag;
        }
    }
}

// ---------------- launch ----------------
extern "C" void kernel_launch(void* const* d_in, const int* in_sizes, int n_in,
                              void* d_out, int out_size) {
    const float* texts  = (const float*)d_in[0];
    const int*   seqlen = (const int*)d_in[1];
    const float* Wih_f  = (const float*)d_in[2];
    const float* Whh_f  = (const float*)d_in[3];
    const float* b_f    = (const float*)d_in[4];
    const float* Wih_b  = (const float*)d_in[5];
    const float* Whh_b  = (const float*)d_in[6];
    const float* b_b    = (const float*)d_in[7];
    const float* W_h2t  = (const float*)d_in[8];
    const float* b_h2t  = (const float*)d_in[9];
    const float* trans  = (const float*)d_in[10];
    float* out = (float*)d_out;

    cudaFuncSetAttribute(lstm_persistent,
                         cudaFuncAttributeMaxDynamicSharedMemorySize, SM_TOT);
    cudaFuncSetAttribute(feats_kernel,
                         cudaFuncAttributeMaxDynamicSharedMemorySize, KK * 1024 * 4);

    init_kernel<<<32, 256>>>();
    xgemm_kernel<<<dim3(G4 / 128, (BB * TT) / 128, 2), 256>>>(texts, Wih_f, Wih_b, b_f, b_b);
    transpose_kernel<<<dim3(32, 512, 2), 256>>>();
    lstm_persistent<<<128, 256, SM_TOT>>>(Whh_f, Whh_b);
    feats_kernel<<<256, 128, KK * 1024 * 4>>>(W_h2t, b_h2t);
    viterbi_kernel<<<BB, 32>>>(trans, seqlen, out);
}

// round 14
// speedup vs baseline: 1.2327x; 1.2327x over previous
#include <cuda_runtime.h>
#include <math.h>

#define BB 64
#define TT 512
#define EE 512
#define HH 512
#define G4 2048
#define KK 23
#define START_TAG 1
#define END_TAG 2
#define NEGV -10000.0f

typedef unsigned long long ull;

__device__ __forceinline__ ull pack2(float lo, float hi) {
    ull r;
    asm("mov.b64 %0, {%1, %2};" : "=l"(r) : "f"(lo), "f"(hi));
    return r;
}
__device__ __forceinline__ void unpack2(ull v, float& lo, float& hi) {
    asm("mov.b64 {%0, %1}, %2;" : "=f"(lo), "=f"(hi) : "l"(v));
}
__device__ __forceinline__ void ffma2(ull& d, ull a, ull b) {
    asm("fma.rn.f32x2 %0, %1, %2, %3;" : "=l"(d) : "l"(a), "l"(b), "l"(d));
}
__device__ __forceinline__ ull addf32x2(ull a, ull b) {
    ull r;
    asm("add.rn.f32x2 %0, %1, %2;" : "=l"(r) : "l"(a), "l"(b));
    return r;
}
__device__ __forceinline__ unsigned s2u(const void* p) {
    unsigned r;
    asm("{ .reg .u64 t; cvta.to.shared.u64 t, %1; cvt.u32.u64 %0, t; }"
        : "=r"(r) : "l"(p));
    return r;
}
#define CPASYNC16(dst, src) \
    asm volatile("cp.async.cg.shared.global [%0], [%1], 16;\n" :: "r"(dst), "l"(src))
#define CPCOMMIT() asm volatile("cp.async.commit_group;\n" ::: "memory")
#define CPWAIT(n)  asm volatile("cp.async.wait_group %0;\n" :: "n"(n) : "memory")

// ---------------- scratch ----------------
__device__ float g_xg[2][67108864];    // [dir][(b*T+t)*2048 + n]
__device__ float g_xgt[2][67108864];   // [dir][(t*2048 + n)*64 + b]
__device__ float g_hs[2][16777216];    // [dir][(t*512 + u)*64 + b]
__device__ float g_zero[HH * BB];
__device__ float g_feats[BB * TT * KK];
__device__ unsigned g_barr[64];        // 8 counters/dir at [dir*32 + c*2]

__global__ void init_kernel() {
    int idx = blockIdx.x * blockDim.x + threadIdx.x;
    for (int i = idx; i < HH * BB; i += gridDim.x * blockDim.x) g_zero[i] = 0.0f;
    if (idx < 64) g_barr[idx] = 0u;
}

// ---------------- input GEMM: reg-buffered pipelined tiles ----------------
__global__ __launch_bounds__(256, 2)
void xgemm_kernel(const float* __restrict__ A,
                  const float* __restrict__ Wf,
                  const float* __restrict__ Wb,
                  const float* __restrict__ bf,
                  const float* __restrict__ bb) {
    const int dir = blockIdx.z;
    const float* __restrict__ W = dir ? Wb : Wf;
    const float* __restrict__ bias = dir ? bb : bf;
    float* __restrict__ C = g_xg[dir];

    __shared__ __align__(16) float2 As2[8][128];
    __shared__ __align__(16) float  Bs[8][128];

    const int tid = threadIdx.x;
    const int m0 = blockIdx.y * 128;
    const int n0 = blockIdx.x * 128;
    const int lrow = tid >> 1;
    const int lkq  = (tid & 1) * 4;
    const int tx = (tid & 15) * 4;
    const int ty = (tid >> 4) * 4;

    ull acc2[8][4];
#pragma unroll
    for (int i = 0; i < 8; i++)
#pragma unroll
        for (int j = 0; j < 4; j++) acc2[i][j] = 0ull;

    // prologue: first tile in regs
    float4 av = *(const float4*)(A + (size_t)(m0 + lrow) * EE + lkq);
    float4 bv = *(const float4*)(W + (size_t)(n0 + lrow) * EE + lkq);

    for (int kt = 0; kt < EE; kt += 8) {
        As2[lkq + 0][lrow] = make_float2(av.x, av.x);
        As2[lkq + 1][lrow] = make_float2(av.y, av.y);
        As2[lkq + 2][lrow] = make_float2(av.z, av.z);
        As2[lkq + 3][lrow] = make_float2(av.w, av.w);
        Bs[lkq + 0][lrow] = bv.x; Bs[lkq + 1][lrow] = bv.y;
        Bs[lkq + 2][lrow] = bv.z; Bs[lkq + 3][lrow] = bv.w;
        __syncthreads();
        // prefetch next tile while computing this one
        if (kt + 8 < EE) {
            av = *(const float4*)(A + (size_t)(m0 + lrow) * EE + kt + 8 + lkq);
            bv = *(const float4*)(W + (size_t)(n0 + lrow) * EE + kt + 8 + lkq);
        }
#pragma unroll
        for (int k = 0; k < 8; k++) {
            ull a[8], b[4];
            {
                ulonglong2 t0 = *(const ulonglong2*)&As2[k][ty];
                ulonglong2 t1 = *(const ulonglong2*)&As2[k][ty + 2];
                ulonglong2 t2 = *(const ulonglong2*)&As2[k][ty + 64];
                ulonglong2 t3 = *(const ulonglong2*)&As2[k][ty + 66];
                a[0] = t0.x; a[1] = t0.y; a[2] = t1.x; a[3] = t1.y;
                a[4] = t2.x; a[5] = t2.y; a[6] = t3.x; a[7] = t3.y;
                ulonglong2 u0 = *(const ulonglong2*)&Bs[k][tx];
                ulonglong2 u1 = *(const ulonglong2*)&Bs[k][tx + 64];
                b[0] = u0.x; b[1] = u0.y; b[2] = u1.x; b[3] = u1.y;
            }
#pragma unroll
            for (int i = 0; i < 8; i++)
#pragma unroll
                for (int j = 0; j < 4; j++)
                    ffma2(acc2[i][j], a[i], b[j]);
        }
        __syncthreads();
    }
    float4 bia0 = *(const float4*)(bias + n0 + tx);
    float4 bia1 = *(const float4*)(bias + n0 + tx + 64);
#pragma unroll
    for (int i = 0; i < 8; i++) {
        int m = m0 + ((i < 4) ? (ty + i) : (ty + 64 + i - 4));
        float l0, h0, l1, h1, l2, h2, l3, h3;
        unpack2(acc2[i][0], l0, h0);
        unpack2(acc2[i][1], l1, h1);
        unpack2(acc2[i][2], l2, h2);
        unpack2(acc2[i][3], l3, h3);
        float4 o0, o1;
        o0.x = l0 + bia0.x; o0.y = h0 + bia0.y;
        o0.z = l1 + bia0.z; o0.w = h1 + bia0.w;
        o1.x = l2 + bia1.x; o1.y = h2 + bia1.y;
        o1.z = l3 + bia1.z; o1.w = h3 + bia1.w;
        *(float4*)(C + (size_t)m * G4 + n0 + tx)      = o0;
        *(float4*)(C + (size_t)m * G4 + n0 + tx + 64) = o1;
    }
}

// ---------------- transpose xg: [(b*T+t)][n] -> [t][n][b] -----------------
__global__ __launch_bounds__(256, 4)
void transpose_kernel() {
    const int dir = blockIdx.z;
    const int t   = blockIdx.y;
    const int n0  = blockIdx.x * 64;
    __shared__ float s[64][65];

    const float* __restrict__ src = g_xg[dir];
    float* __restrict__ dst = g_xgt[dir];
    const int tid = threadIdx.x;

#pragma unroll
    for (int i = 0; i < 4; i++) {
        int e = i * 256 + tid;
        int b = e >> 4;
        int nf = e & 15;
        float4 v = *(const float4*)(src + ((size_t)b * TT + t) * G4 + n0 + nf * 4);
        s[b][nf * 4 + 0] = v.x; s[b][nf * 4 + 1] = v.y;
        s[b][nf * 4 + 2] = v.z; s[b][nf * 4 + 3] = v.w;
    }
    __syncthreads();
#pragma unroll
    for (int i = 0; i < 4; i++) {
        int e = i * 256 + tid;
        int nl = e >> 4;
        int bf = e & 15;
        float4 w;
        w.x = s[bf * 4 + 0][nl]; w.y = s[bf * 4 + 1][nl];
        w.z = s[bf * 4 + 2][nl]; w.w = s[bf * 4 + 3][nl];
        *(float4*)(dst + ((size_t)t * G4 + n0 + nl) * BB + bf * 4) = w;
    }
}

// ---------------- persistent bidirectional LSTM (R7 core) -----------------
__device__ __forceinline__ float sigf(float x) {
    return 1.0f / (1.0f + __expf(-x));
}
__device__ __forceinline__ float tanhfast(float x) {
    return 1.0f - 2.0f / (__expf(2.0f * x) + 1.0f);
}

#define USTR 2050
#define WB_B (8 * USTR * 8)            // 131200 bytes
#define HB_OFF WB_B                    // 2 grp x 2 buf x 16KB = 65536
#define PART_OFF (WB_B + 65536)        // 128 x 9 ull = 9216 bytes
#define SM_TOT (PART_OFF + 9216)

__global__ __launch_bounds__(256, 1)
void lstm_persistent(const float* __restrict__ Whh_f,
                     const float* __restrict__ Whh_b) {
    const int blk  = blockIdx.x;
    const int dir  = blk >> 6;
    const int ublk = blk & 63;
    const float* __restrict__ Whh = dir ? Whh_b : Whh_f;

    extern __shared__ __align__(16) char sm[];
    float2* __restrict__ wsm = (float2*)sm;
    float*  __restrict__ hq  = (float*)(sm + HB_OFF);
    ull*    __restrict__ part = (ull*)(sm + PART_OFF);

    const int tid  = threadIdx.x;
    const int warp = tid >> 5;
    const int lane = tid & 31;
    const int kgrp = warp >> 2;            // 0 or 1 (k-half)
    const int wu2  = warp & 3;
    const int half = lane >> 4;
    const int l16  = lane & 15;
    const int gtid = tid & 127;            // id within k-group
    const int ulocal = wu2 * 2 + half;     // 0..7
    const int u = ublk * 8 + ulocal;

    // load + duplicate weights: wsm[ul*USTR + g*512 + k] = (w,w)
    for (int idx = tid; idx < 8 * 4 * HH; idx += 256) {
        int ul = idx >> 11;
        int r  = idx & 2047;
        int g  = r >> 9;
        int k  = r & 511;
        float v = Whh[(size_t)(g * HH + ublk * 8 + ul) * HH + k];
        wsm[ul * USTR + r] = make_float2(v, v);
    }
    __syncthreads();

    const float2* __restrict__ wu_ = wsm + ulocal * USTR;
    float* __restrict__ myb[2] = { hq + kgrp * 8192, hq + kgrp * 8192 + 4096 };
    const unsigned bu[2] = { s2u(myb[0]), s2u(myb[1]) };
    const float* __restrict__ xgt = g_xgt[dir];
    float* __restrict__ hsd = g_hs[dir];
    unsigned* __restrict__ barr = g_barr + dir * 32;

    float cst[4] = {0.f, 0.f, 0.f, 0.f};

    for (int s = 0; s < TT; s++) {
        const int t = dir ? (TT - 1 - s) : s;
        const float* __restrict__ hsrc = (s == 0) ? g_zero
            : (hsd + (size_t)(dir ? t + 1 : t - 1) * HH * BB);

        // group0 prefetches gate inputs (independent of h)
        float4 xv[4];
        if (kgrp == 0) {
#pragma unroll
            for (int g = 0; g < 4; g++)
                xv[g] = *(const float4*)(xgt +
                    ((size_t)t * G4 + g * HH + u) * BB + 4 * l16);
        }

        // stage 16KB chunk j of this k-group into buffer j&1 (group-local)
#define STAGE(j) do {                                                        \
            unsigned dstb = bu[(j) & 1];                                     \
            const float* srcb = hsrc + (kgrp * 4 + (j)) * 64 * BB;           \
            _Pragma("unroll")                                                \
            for (int i = 0; i < 8; i++) {                                    \
                int e = i * 128 + gtid;                                      \
                int kl = e >> 4, b4 = e & 15;                                \
                CPASYNC16(dstb + (kl * 64 + b4 * 4) * 4,                     \
                          srcb + kl * 64 + b4 * 4);                          \
            }                                                                \
            CPCOMMIT();                                                      \
        } while (0)
#define BARG() asm volatile("bar.sync %0, 128;" :: "r"(kgrp + 1) : "memory")

        STAGE(0);
        STAGE(1);

        ull a0[4], a1[4];
#pragma unroll
        for (int g = 0; g < 4; g++) { a0[g] = 0ull; a1[g] = 0ull; }

#pragma unroll
        for (int j = 0; j < 4; j++) {
            if (j < 3) { CPWAIT(1); } else { CPWAIT(0); }
            BARG();
            const float* __restrict__ hc = myb[j & 1];
            const int kb = (kgrp * 4 + j) * 64;
#pragma unroll 8
            for (int kk = 0; kk < 64; kk += 2) {
                const int k = kb + kk;
                ulonglong2 wi = *(const ulonglong2*)(wu_ + k);
                ulonglong2 wf = *(const ulonglong2*)(wu_ + 512 + k);
                ulonglong2 wg = *(const ulonglong2*)(wu_ + 1024 + k);
                ulonglong2 wo = *(const ulonglong2*)(wu_ + 1536 + k);
                ulonglong2 h0 = *(const ulonglong2*)&hc[kk * 64 + 4 * l16];
                ulonglong2 h1 = *(const ulonglong2*)&hc[(kk + 1) * 64 + 4 * l16];
                ffma2(a0[0], wi.x, h0.x); ffma2(a1[0], wi.x, h0.y);
                ffma2(a0[1], wf.x, h0.x); ffma2(a1[1], wf.x, h0.y);
                ffma2(a0[2], wg.x, h0.x); ffma2(a1[2], wg.x, h0.y);
                ffma2(a0[3], wo.x, h0.x); ffma2(a1[3], wo.x, h0.y);
                ffma2(a0[0], wi.y, h1.x); ffma2(a1[0], wi.y, h1.y);
                ffma2(a0[1], wf.y, h1.x); ffma2(a1[1], wf.y, h1.y);
                ffma2(a0[2], wg.y, h1.x); ffma2(a1[2], wg.y, h1.y);
                ffma2(a0[3], wo.y, h1.x); ffma2(a1[3], wo.y, h1.y);
            }
            if (j < 2) {
                BARG();          // group warps done reading buffer j&1
                STAGE(j + 2);
            }
        }
#undef STAGE

        // reduction: k-high group publishes partials, k-low finalizes
        __syncthreads();
        if (kgrp == 1) {
#pragma unroll
            for (int g = 0; g < 4; g++) {
                part[gtid * 9 + g]     = a0[g];
                part[gtid * 9 + 4 + g] = a1[g];
            }
        }
        __syncthreads();
        if (kgrp == 0) {
            float pre[4][4];
#pragma unroll
            for (int g = 0; g < 4; g++) {
                ull s0 = addf32x2(a0[g], part[gtid * 9 + g]);
                ull s1 = addf32x2(a1[g], part[gtid * 9 + 4 + g]);
                unpack2(s0, pre[g][0], pre[g][1]);
                unpack2(s1, pre[g][2], pre[g][3]);
                pre[g][0] += ((const float*)&xv[g])[0];
                pre[g][1] += ((const float*)&xv[g])[1];
                pre[g][2] += ((const float*)&xv[g])[2];
                pre[g][3] += ((const float*)&xv[g])[3];
            }
            float4 hv;
            float* hvp = (float*)&hv;
#pragma unroll
            for (int b = 0; b < 4; b++) {
                float ig = sigf(pre[0][b]);
                float fg = sigf(pre[1][b]);
                float gg = tanhfast(pre[2][b]);
                float og = sigf(pre[3][b]);
                float cn = fg * cst[b] + ig * gg;
                cst[b] = cn;
                hvp[b] = og * tanhfast(cn);
            }
            *(float4*)(hsd + ((size_t)t * HH + u) * BB + 4 * l16) = hv;
        }

        // global barrier: 8 spread counters per dir, warp-0 collective poll
        if (s != TT - 1) {
            __syncthreads();
            if (tid == 0) {
                __threadfence();   // release: h stores visible before arrive
                atomicAdd(&barr[(ublk & 7) * 2], 1u);
            }
            if (warp == 0) {
                const unsigned target = 8u * (unsigned)(s + 1);
                const bool need = lane < 8;
                for (;;) {
                    unsigned v = need
                        ? *((volatile unsigned*)&barr[lane * 2]) : target;
                    if (!__ballot_sync(0xffffffffu, v < target)) break;
                    __nanosleep(32);
                }
            }
            __syncthreads();
            // no acquire fence needed: h is read via cp.async.cg (L2-direct)
        }
    }
}

// ---------------- emissions: feats = [h_f, h_b] @ W_h2t^T + b_h2t ---------
__global__ __launch_bounds__(128, 2)
void feats_kernel(const float* __restrict__ Wh2t,
                  const float* __restrict__ bh2t) {
    extern __shared__ float Ws[];  // [23][1024]
    const int tid = threadIdx.x;
    for (int i = tid; i < KK * 1024; i += 128) Ws[i] = Wh2t[i];
    __syncthreads();

    const int w    = tid >> 5;
    const int lane = tid & 31;
    const int t    = blockIdx.x * 2 + (w >> 1);
    const int b    = (w & 1) * 32 + lane;

    ull acc2[KK];
#pragma unroll
    for (int k = 0; k < KK; k++) acc2[k] = 0ull;

    const float* __restrict__ hf = g_hs[0] + (size_t)t * HH * BB;
#pragma unroll 4
    for (int j = 0; j < HH; j += 2) {
        ull hp = pack2(hf[j * BB + b], hf[(j + 1) * BB + b]);
#pragma unroll
        for (int k = 0; k < KK; k++) {
            ull wp = *(const ull*)&Ws[k * 1024 + j];
            ffma2(acc2[k], wp, hp);
        }
    }
    const float* __restrict__ hbv = g_hs[1] + (size_t)t * HH * BB;
#pragma unroll 4
    for (int j = 0; j < HH; j += 2) {
        ull hp = pack2(hbv[j * BB + b], hbv[(j + 1) * BB + b]);
#pragma unroll
        for (int k = 0; k < KK; k++) {
            ull wp = *(const ull*)&Ws[k * 1024 + HH + j];
            ffma2(acc2[k], wp, hp);
        }
    }
#pragma unroll
    for (int k = 0; k < KK; k++) {
        float lo, hi;
        unpack2(acc2[k], lo, hi);
        g_feats[((size_t)b * TT + t) * KK + k] = lo + hi + __ldg(bh2t + k);
    }
}

// ---------------- Viterbi ----------------
__global__ void viterbi_kernel(const float* __restrict__ trans,
                               const int* __restrict__ seq_len,
                               float* __restrict__ out) {
    const int b    = blockIdx.x;
    const int lane = threadIdx.x;
    __shared__ unsigned char bp[TT][24];

    const int L = seq_len[b];
    const bool active = lane < KK;

    float tr[KK];
#pragma unroll
    for (int p = 0; p < KK; p++)
        tr[p] = active ? trans[lane * KK + p] : -3.0e38f;

    float fv = (lane == START_TAG) ? 0.0f : NEGV;
    const float* __restrict__ fb = g_feats + (size_t)b * TT * KK;

    for (int t = 0; t < TT; t++) {
        float ft = active ? fb[t * KK + lane] : 0.0f;
        float best = -3.4e38f;
        int arg = 0;
#pragma unroll
        for (int p = 0; p < KK; p++) {
            float v = __shfl_sync(0xffffffffu, fv, p) + tr[p];
            if (v > best) { best = v; arg = p; }
        }
        const bool m = (t < L);
        if (m) fv = best + ft;
        if (active) bp[t][lane] = m ? (unsigned char)arg : (unsigned char)lane;
    }

    float term = active ? (fv + trans[END_TAG * KK + lane]) : -3.4e38f;
    float bestv = -3.4e38f;
    int btag = 0;
#pragma unroll
    for (int p = 0; p < KK; p++) {
        float v = __shfl_sync(0xffffffffu, term, p);
        if (v > bestv) { bestv = v; btag = p; }
    }

    if (lane == 0) {
        out[b] = bestv;
        int tag = btag;
        out[BB + (size_t)b * TT + (TT - 1)] = (float)tag;
        for (int t = TT - 1; t >= 1; t--) {
            tag = bp[t][tag];
            out[BB + (size_t)b * TT + (t - 1)] = (float)tag;
        }
    }
}

// ---------------- launch ----------------
extern "C" void kernel_launch(void* const* d_in, const int* in_sizes, int n_in,
                              void* d_out, int out_size) {
    const float* texts  = (const float*)d_in[0];
    const int*   seqlen = (const int*)d_in[1];
    const float* Wih_f  = (const float*)d_in[2];
    const float* Whh_f  = (const float*)d_in[3];
    const float* b_f    = (const float*)d_in[4];
    const float* Wih_b  = (const float*)d_in[5];
    const float* Whh_b  = (const float*)d_in[6];
    const float* b_b    = (const float*)d_in[7];
    const float* W_h2t  = (const float*)d_in[8];
    const float* b_h2t  = (const float*)d_in[9];
    const float* trans  = (const float*)d_in[10];
    float* out = (float*)d_out;

    cudaFuncSetAttribute(lstm_persistent,
                         cudaFuncAttributeMaxDynamicSharedMemorySize, SM_TOT);
    cudaFuncSetAttribute(feats_kernel,
                         cudaFuncAttributeMaxDynamicSharedMemorySize, KK * 1024 * 4);

    init_kernel<<<32, 256>>>();
    xgemm_kernel<<<dim3(G4 / 128, (BB * TT) / 128, 2), 256>>>(texts, Wih_f, Wih_b, b_f, b_b);
    transpose_kernel<<<dim3(32, 512, 2), 256>>>();
    lstm_persistent<<<128, 256, SM_TOT>>>(Whh_f, Whh_b);
    feats_kernel<<<256, 128, KK * 1024 * 4>>>(W_h2t, b_h2t);
    viterbi_kernel<<<BB, 32>>>(trans, seqlen, out);
}